// round 2
// baseline (speedup 1.0000x reference)
#include <cuda_runtime.h>
#include <math.h>

#define Bb 4
#define Ll 2048
#define DM 1024
#define DI 2048
#define DS 16
#define DCONV 4
#define DTR 64
#define NROWS (Bb*Ll)          // 8192
#define PROJW (DTR + 2*DS)     // 96

// ---------------- scratch (static device globals; no allocation) ----------------
__device__ float g_xn [NROWS * DM];        // 33.5 MB
__device__ float g_xz [NROWS * 2 * DI];    // 134 MB  (u | z)
__device__ float g_uc [NROWS * DI];        // 67 MB
__device__ float g_proj[NROWS * PROJW];    // 3.1 MB
__device__ float g_dt [NROWS * DI];        // 67 MB
__device__ float g_y  [NROWS * DI];        // 67 MB
__device__ float g_o  [NROWS * DM];        // 33.5 MB

// ---------------- LayerNorm: one block per row of 1024 ----------------
__global__ void ln_kernel(const float* __restrict__ x,
                          const float* __restrict__ gma,
                          const float* __restrict__ bta,
                          float* __restrict__ xn) {
    int row = blockIdx.x;
    const float4* xr = (const float4*)(x + row * DM);
    float4 v = xr[threadIdx.x];               // 256 threads * 4 = 1024
    float s  = v.x + v.y + v.z + v.w;
    float ss = v.x*v.x + v.y*v.y + v.z*v.z + v.w*v.w;
    #pragma unroll
    for (int o = 16; o; o >>= 1) {
        s  += __shfl_xor_sync(0xffffffffu, s,  o);
        ss += __shfl_xor_sync(0xffffffffu, ss, o);
    }
    __shared__ float sh_s[8], sh_ss[8];
    int wid = threadIdx.x >> 5, lane = threadIdx.x & 31;
    if (lane == 0) { sh_s[wid] = s; sh_ss[wid] = ss; }
    __syncthreads();
    if (threadIdx.x == 0) {
        float a = 0.f, b2 = 0.f;
        #pragma unroll
        for (int i = 0; i < 8; ++i) { a += sh_s[i]; b2 += sh_ss[i]; }
        sh_s[0] = a; sh_ss[0] = b2;
    }
    __syncthreads();
    float mu  = sh_s[0]  * (1.f / DM);
    float var = sh_ss[0] * (1.f / DM) - mu * mu;
    float inv = rsqrtf(var + 1e-5f);
    const float4* gv4 = (const float4*)gma;
    const float4* bv4 = (const float4*)bta;
    float4 gv = gv4[threadIdx.x], bv = bv4[threadIdx.x];
    float4 out;
    out.x = (v.x - mu) * inv * gv.x + bv.x;
    out.y = (v.y - mu) * inv * gv.y + bv.y;
    out.z = (v.z - mu) * inv * gv.z + bv.z;
    out.w = (v.w - mu) * inv * gv.w + bv.w;
    ((float4*)(xn + row * DM))[threadIdx.x] = out;
}

// ---------------- generic SGEMM: C[M,N] = A[M,K] * B[N,K]^T ----------------
// A row-major lda, B row-major ldb (K contiguous), C row-major ldc.
// M % 128 == 0, K % 8 == 0, N % 32 == 0 (bounds-checked on N).
#define BM 128
#define BN 128
#define BK 8
#define TM 8
#define TN 8
__global__ __launch_bounds__(256, 2)
void sgemm_nt(const float* __restrict__ A, const float* __restrict__ B,
              float* __restrict__ C, int M, int N, int K,
              int lda, int ldb, int ldc) {
    __shared__ float As[BK][BM + 4];
    __shared__ float Bs[BK][BN + 4];
    int bm = blockIdx.y * BM, bn = blockIdx.x * BN;
    int tid = threadIdx.x;
    int lr = tid >> 1;            // 0..127 tile row
    int lc = (tid & 1) * 4;       // k offset 0 or 4
    int tx = tid & 15, ty = tid >> 4;
    int row0 = ty * TM, col0 = tx * TN;
    float acc[TM][TN];
    #pragma unroll
    for (int i = 0; i < TM; ++i)
        #pragma unroll
        for (int j = 0; j < TN; ++j) acc[i][j] = 0.f;

    const float* Ap = A + (bm + lr) * lda + lc;
    int brow = bn + lr;
    const float* Bp = B + brow * ldb + lc;
    bool bok = (brow < N);

    for (int k0 = 0; k0 < K; k0 += BK) {
        float4 av = *(const float4*)(Ap + k0);
        As[lc+0][lr] = av.x; As[lc+1][lr] = av.y;
        As[lc+2][lr] = av.z; As[lc+3][lr] = av.w;
        float4 bv = make_float4(0.f, 0.f, 0.f, 0.f);
        if (bok) bv = *(const float4*)(Bp + k0);
        Bs[lc+0][lr] = bv.x; Bs[lc+1][lr] = bv.y;
        Bs[lc+2][lr] = bv.z; Bs[lc+3][lr] = bv.w;
        __syncthreads();
        #pragma unroll
        for (int k = 0; k < BK; ++k) {
            float ra[TM], rb[TN];
            *(float4*)&ra[0] = *(const float4*)&As[k][row0];
            *(float4*)&ra[4] = *(const float4*)&As[k][row0 + 4];
            *(float4*)&rb[0] = *(const float4*)&Bs[k][col0];
            *(float4*)&rb[4] = *(const float4*)&Bs[k][col0 + 4];
            #pragma unroll
            for (int i = 0; i < TM; ++i)
                #pragma unroll
                for (int j = 0; j < TN; ++j)
                    acc[i][j] = fmaf(ra[i], rb[j], acc[i][j]);
        }
        __syncthreads();
    }
    // store (N always multiple of 32 -> float4 groups fully in/out)
    #pragma unroll
    for (int i = 0; i < TM; ++i) {
        float* Cr = C + (bm + row0 + i) * ldc + bn + col0;
        if (bn + col0 < N)     *(float4*)(Cr)     = *(float4*)&acc[i][0];
        if (bn + col0 + 4 < N) *(float4*)(Cr + 4) = *(float4*)&acc[i][4];
    }
}

// ---------------- depthwise causal conv (K=4) + SiLU ----------------
__global__ void conv_silu_kernel(const float* __restrict__ cw,
                                 const float* __restrict__ cb,
                                 float* __restrict__ uc) {
    int idx = blockIdx.x * blockDim.x + threadIdx.x;
    if (idx >= NROWS * DI) return;
    int d = idx & (DI - 1);
    int l = (idx >> 11) & (Ll - 1);
    int b = idx >> 22;                 // / (Ll*DI)
    float acc = cb[d];
    const float* base = g_xz + ((b * Ll) << 12) + d;   // u half, row stride 4096
    #pragma unroll
    for (int k = 0; k < DCONV; ++k) {
        int ls = l + k - (DCONV - 1);
        if (ls >= 0) acc = fmaf(base[ls << 12], cw[d * DCONV + k], acc);
    }
    float sig = 1.f / (1.f + __expf(-acc));
    uc[idx] = acc * sig;
}

// ---------------- dt epilogue: bias + softplus (in place) ----------------
__global__ void dt_softplus_kernel(const float* __restrict__ dtb) {
    int idx = blockIdx.x * blockDim.x + threadIdx.x;
    if (idx >= NROWS * DI) return;
    float v = g_dt[idx] + dtb[idx & (DI - 1)];
    g_dt[idx] = (v > 20.f) ? v : log1pf(expf(v));
}

// ---------------- selective scan: 16 lanes (states) per channel ----------------
__global__ void scan_kernel(const float* __restrict__ A_log,
                            const float* __restrict__ D_param) {
    int warp = threadIdx.x >> 5;
    int lane = threadIdx.x & 31;
    int half = lane >> 4;
    int n    = lane & 15;
    int ch = blockIdx.x * 16 + warp * 2 + half;   // 0..8191
    int b = ch >> 11;
    int d = ch & (DI - 1);
    float Av = -__expf(A_log[d * DS + n]);
    float Dv = D_param[d];
    int base = b * Ll;
    float h = 0.f;
    // prefetch t=0
    float dtv = g_dt [base * DI + d];
    float uv  = g_uc [base * DI + d];
    float Bv  = g_proj[base * PROJW + DTR + n];
    float Cv  = g_proj[base * PROJW + DTR + DS + n];
    for (int t = 0; t < Ll; ++t) {
        float dt_c = dtv, u_c = uv, B_c = Bv, C_c = Cv;
        if (t + 1 < Ll) {
            dtv = g_dt [(base + t + 1) * DI + d];
            uv  = g_uc [(base + t + 1) * DI + d];
            Bv  = g_proj[(base + t + 1) * PROJW + DTR + n];
            Cv  = g_proj[(base + t + 1) * PROJW + DTR + DS + n];
        }
        float dA = __expf(dt_c * Av);
        h = fmaf(h, dA, dt_c * u_c * B_c);
        float yv = h * C_c;
        yv += __shfl_xor_sync(0xffffffffu, yv, 8, 16);
        yv += __shfl_xor_sync(0xffffffffu, yv, 4, 16);
        yv += __shfl_xor_sync(0xffffffffu, yv, 2, 16);
        yv += __shfl_xor_sync(0xffffffffu, yv, 1, 16);
        if (n == 0) {
            float zv = g_xz[((base + t) << 12) + DI + d];
            float sig = 1.f / (1.f + __expf(-zv));
            g_y[(base + t) * DI + d] = (yv + u_c * Dv) * (zv * sig);
        }
    }
}

// ---------------- final: exact GELU + residual ----------------
__global__ void gelu_add_kernel(const float* __restrict__ x,
                                float* __restrict__ out) {
    int idx = blockIdx.x * blockDim.x + threadIdx.x;
    if (idx >= NROWS * DM) return;
    float v = g_o[idx];
    float g = 0.5f * v * (1.f + erff(v * 0.70710678118654752f));
    out[idx] = g + x[idx];
}

// ---------------- launch ----------------
extern "C" void kernel_launch(void* const* d_in, const int* in_sizes, int n_in,
                              void* d_out, int out_size) {
    const float* x        = (const float*)d_in[0];
    const float* gamma    = (const float*)d_in[1];
    const float* beta     = (const float*)d_in[2];
    const float* in_w     = (const float*)d_in[3];   // [4096,1024]
    const float* conv_w   = (const float*)d_in[4];   // [2048,4]
    const float* conv_b   = (const float*)d_in[5];
    const float* xproj_w  = (const float*)d_in[6];   // [96,2048]
    const float* dtproj_w = (const float*)d_in[7];   // [2048,64]
    const float* dtproj_b = (const float*)d_in[8];
    const float* A_log    = (const float*)d_in[9];   // [2048,16]
    const float* D_param  = (const float*)d_in[10];
    const float* outw     = (const float*)d_in[11];  // [1024,2048]
    float* out = (float*)d_out;

    float *xn, *xz, *uc, *proj, *dt, *y, *o;
    cudaGetSymbolAddress((void**)&xn,   g_xn);
    cudaGetSymbolAddress((void**)&xz,   g_xz);
    cudaGetSymbolAddress((void**)&uc,   g_uc);
    cudaGetSymbolAddress((void**)&proj, g_proj);
    cudaGetSymbolAddress((void**)&dt,   g_dt);
    cudaGetSymbolAddress((void**)&y,    g_y);
    cudaGetSymbolAddress((void**)&o,    g_o);

    // 1. layernorm
    ln_kernel<<<NROWS, 256>>>(x, gamma, beta, xn);

    // 2. in_proj: [8192,4096] = xn[8192,1024] * in_w[4096,1024]^T
    {
        dim3 grid(2 * DI / BN, NROWS / BM);
        sgemm_nt<<<grid, 256>>>(xn, in_w, xz, NROWS, 2 * DI, DM, DM, DM, 2 * DI);
    }

    // 3. conv + silu
    conv_silu_kernel<<<(NROWS * DI + 255) / 256, 256>>>(conv_w, conv_b, uc);

    // 4. x_proj: [8192,96] = uc[8192,2048] * xproj_w[96,2048]^T
    {
        dim3 grid((PROJW + BN - 1) / BN, NROWS / BM);
        sgemm_nt<<<grid, 256>>>(uc, xproj_w, proj, NROWS, PROJW, DI, DI, DI, PROJW);
    }

    // 5. dt_proj: [8192,2048] = proj[:, :64] * dtproj_w[2048,64]^T
    {
        dim3 grid(DI / BN, NROWS / BM);
        sgemm_nt<<<grid, 256>>>(proj, dtproj_w, dt, NROWS, DI, DTR, PROJW, DTR, DI);
    }
    dt_softplus_kernel<<<(NROWS * DI + 255) / 256, 256>>>(dtproj_b);

    // 6. selective scan (+ u*D + silu(z) fused)
    scan_kernel<<<Bb * DI / 16, 256>>>(A_log, D_param);

    // 7. out_proj: [8192,1024] = y[8192,2048] * outw[1024,2048]^T
    {
        dim3 grid(DM / BN, NROWS / BM);
        sgemm_nt<<<grid, 256>>>(y, outw, o, NROWS, DM, DI, DI, DI, DM);
    }

    // 8. gelu + skip
    gelu_add_kernel<<<(NROWS * DM + 255) / 256, 256>>>(x, out);
}

// round 3
// speedup vs baseline: 1.1134x; 1.1134x over previous
#include <cuda_runtime.h>
#include <math.h>

#define Bb 4
#define Ll 2048
#define DM 1024
#define DI 2048
#define DS 16
#define DCONV 4
#define DTR 64
#define NROWS (Bb*Ll)          // 8192
#define PROJW (DTR + 2*DS)     // 96

typedef unsigned long long u64;

// ---------------- scratch (static device globals; no allocation) ----------------
__device__ float g_xn [NROWS * DM];        // 33.5 MB
__device__ float g_xz [NROWS * 2 * DI];    // 134 MB  (u | z)
__device__ float g_uc [NROWS * DI];        // 67 MB
__device__ float g_proj[NROWS * PROJW];    // 3.1 MB
__device__ float g_dt [NROWS * DI];        // 67 MB
__device__ float g_y  [NROWS * DI];        // 67 MB

// ---------------- packed f32x2 helpers ----------------
__device__ __forceinline__ u64 pack2(float x, float y) {
    u64 r; asm("mov.b64 %0, {%1, %2};" : "=l"(r) : "f"(x), "f"(y)); return r;
}
__device__ __forceinline__ void fma2(u64& d, u64 a, u64 b) {
    asm("fma.rn.f32x2 %0, %1, %2, %3;" : "=l"(d) : "l"(a), "l"(b), "l"(d));
}
__device__ __forceinline__ void unpack2(u64 v, float& lo, float& hi) {
    asm("mov.b64 {%0, %1}, %2;" : "=f"(lo), "=f"(hi) : "l"(v));
}

// ---------------- LayerNorm: one block per row of 1024 ----------------
__global__ void ln_kernel(const float* __restrict__ x,
                          const float* __restrict__ gma,
                          const float* __restrict__ bta,
                          float* __restrict__ xn) {
    int row = blockIdx.x;
    const float4* xr = (const float4*)(x + row * DM);
    float4 v = xr[threadIdx.x];               // 256 threads * 4 = 1024
    float s  = v.x + v.y + v.z + v.w;
    float ss = v.x*v.x + v.y*v.y + v.z*v.z + v.w*v.w;
    #pragma unroll
    for (int o = 16; o; o >>= 1) {
        s  += __shfl_xor_sync(0xffffffffu, s,  o);
        ss += __shfl_xor_sync(0xffffffffu, ss, o);
    }
    __shared__ float sh_s[8], sh_ss[8];
    int wid = threadIdx.x >> 5, lane = threadIdx.x & 31;
    if (lane == 0) { sh_s[wid] = s; sh_ss[wid] = ss; }
    __syncthreads();
    if (threadIdx.x == 0) {
        float a = 0.f, b2 = 0.f;
        #pragma unroll
        for (int i = 0; i < 8; ++i) { a += sh_s[i]; b2 += sh_ss[i]; }
        sh_s[0] = a; sh_ss[0] = b2;
    }
    __syncthreads();
    float mu  = sh_s[0]  * (1.f / DM);
    float var = sh_ss[0] * (1.f / DM) - mu * mu;
    float inv = rsqrtf(var + 1e-5f);
    const float4* gv4 = (const float4*)gma;
    const float4* bv4 = (const float4*)bta;
    float4 gv = gv4[threadIdx.x], bv = bv4[threadIdx.x];
    float4 out;
    out.x = (v.x - mu) * inv * gv.x + bv.x;
    out.y = (v.y - mu) * inv * gv.y + bv.y;
    out.z = (v.z - mu) * inv * gv.z + bv.z;
    out.w = (v.w - mu) * inv * gv.w + bv.w;
    ((float4*)(xn + row * DM))[threadIdx.x] = out;
}

// ---------------- GEMM: C[M,N] = A[M,K] * B[N,K]^T, double-buffered, f32x2 ----
// EPI: 0 = plain, 1 = +bias then softplus, 2 = gelu + residual
#define BKq 16
template<int BM_, int BN_, int TM_, int TN_, int EPI>
__global__ __launch_bounds__(256, 2)
void gemm_kernel(const float* __restrict__ A, const float* __restrict__ B,
                 float* __restrict__ C, int M, int N, int K,
                 int lda, int ldb, int ldc,
                 const float* __restrict__ bias, const float* __restrict__ res) {
    constexpr int ACH = BM_ / 64;   // float4 chunks per thread for A tile
    constexpr int BCH = BN_ / 64;
    __shared__ float As[2][BKq][BM_ + 4];
    __shared__ float Bs[2][BKq][BN_ + 4];

    int tid = threadIdx.x;
    int bm = blockIdx.y * BM_, bn = blockIdx.x * BN_;
    int tx = tid & 15, ty = tid >> 4;
    int row0 = ty * TM_, col0 = tx * TN_;

    float4 stgA[ACH], stgB[BCH];

    auto loadG = [&](int k0) {
        #pragma unroll
        for (int c = 0; c < ACH; ++c) {
            int cid = tid + 256 * c; int r = cid >> 2; int kq = (cid & 3) << 2;
            stgA[c] = *(const float4*)(A + (size_t)(bm + r) * lda + k0 + kq);
        }
        #pragma unroll
        for (int c = 0; c < BCH; ++c) {
            int cid = tid + 256 * c; int r = cid >> 2; int kq = (cid & 3) << 2;
            float4 v = make_float4(0.f, 0.f, 0.f, 0.f);
            if (bn + r < N) v = *(const float4*)(B + (size_t)(bn + r) * ldb + k0 + kq);
            stgB[c] = v;
        }
    };
    auto storeS = [&](int s) {
        #pragma unroll
        for (int c = 0; c < ACH; ++c) {
            int cid = tid + 256 * c; int r = cid >> 2; int kq = (cid & 3) << 2;
            As[s][kq+0][r] = stgA[c].x; As[s][kq+1][r] = stgA[c].y;
            As[s][kq+2][r] = stgA[c].z; As[s][kq+3][r] = stgA[c].w;
        }
        #pragma unroll
        for (int c = 0; c < BCH; ++c) {
            int cid = tid + 256 * c; int r = cid >> 2; int kq = (cid & 3) << 2;
            Bs[s][kq+0][r] = stgB[c].x; Bs[s][kq+1][r] = stgB[c].y;
            Bs[s][kq+2][r] = stgB[c].z; Bs[s][kq+3][r] = stgB[c].w;
        }
    };

    u64 acc[TM_][TN_/2];
    #pragma unroll
    for (int i = 0; i < TM_; ++i)
        #pragma unroll
        for (int j = 0; j < TN_/2; ++j) acc[i][j] = 0ull;

    loadG(0);
    storeS(0);
    __syncthreads();

    int cur = 0;
    for (int k0 = 0; k0 < K; k0 += BKq) {
        bool more = (k0 + BKq) < K;
        if (more) loadG(k0 + BKq);

        #pragma unroll
        for (int k = 0; k < BKq; ++k) {
            float ra[TM_];
            #pragma unroll
            for (int i = 0; i < TM_; i += 4)
                *(float4*)&ra[i] = *(const float4*)&As[cur][k][row0 + i];
            union { float4 f; u64 d[2]; } ub0, ub1;
            ub0.f = *(const float4*)&Bs[cur][k][col0];
            ub1.f = *(const float4*)&Bs[cur][k][col0 + 4];
            u64 rb2[4] = { ub0.d[0], ub0.d[1], ub1.d[0], ub1.d[1] };
            #pragma unroll
            for (int i = 0; i < TM_; ++i) {
                u64 a2 = pack2(ra[i], ra[i]);
                #pragma unroll
                for (int jj = 0; jj < 4; ++jj) fma2(acc[i][jj], a2, rb2[jj]);
            }
        }

        if (more) {
            storeS(cur ^ 1);
            __syncthreads();
            cur ^= 1;
        }
    }

    // epilogue
    #pragma unroll
    for (int i = 0; i < TM_; ++i) {
        int r = bm + row0 + i;
        float v[TN_];
        #pragma unroll
        for (int jj = 0; jj < TN_/2; ++jj) unpack2(acc[i][jj], v[2*jj], v[2*jj+1]);
        #pragma unroll
        for (int j = 0; j < TN_; ++j) {
            int col = bn + col0 + j;
            if (EPI == 1) {
                float t = v[j] + bias[col];
                v[j] = (t > 20.f) ? t : log1pf(expf(t));
            } else if (EPI == 2) {
                float t = v[j];
                float g = 0.5f * t * (1.f + erff(t * 0.70710678118654752f));
                v[j] = g + res[(size_t)r * ldc + col];
            }
        }
        if (bn + col0 < N) {
            float* Cr = C + (size_t)r * ldc + bn + col0;
            *(float4*)(Cr)     = *(float4*)&v[0];
            *(float4*)(Cr + 4) = *(float4*)&v[4];
        }
    }
}

// ---------------- depthwise causal conv (K=4) + SiLU ----------------
__global__ void conv_silu_kernel(const float* __restrict__ cw,
                                 const float* __restrict__ cb,
                                 float* __restrict__ uc) {
    int idx = blockIdx.x * blockDim.x + threadIdx.x;
    if (idx >= NROWS * DI) return;
    int d = idx & (DI - 1);
    int l = (idx >> 11) & (Ll - 1);
    int b = idx >> 22;
    float acc = cb[d];
    const float* base = g_xz + ((size_t)(b * Ll) << 12) + d;   // u half, stride 4096
    #pragma unroll
    for (int k = 0; k < DCONV; ++k) {
        int ls = l + k - (DCONV - 1);
        if (ls >= 0) acc = fmaf(base[(size_t)ls << 12], cw[d * DCONV + k], acc);
    }
    float sig = 1.f / (1.f + __expf(-acc));
    uc[idx] = acc * sig;
}

// ---------------- selective scan: 16 lanes (states) per channel ----------------
__global__ void scan_kernel(const float* __restrict__ A_log,
                            const float* __restrict__ D_param) {
    int warp = threadIdx.x >> 5;
    int lane = threadIdx.x & 31;
    int half = lane >> 4;
    int n    = lane & 15;
    int ch = blockIdx.x * 16 + warp * 2 + half;   // 0..8191
    int b = ch >> 11;
    int d = ch & (DI - 1);
    float Av = -__expf(A_log[d * DS + n]);
    float Dv = D_param[d];
    int base = b * Ll;
    float h = 0.f;
    float dtv = g_dt [(size_t)base * DI + d];
    float uv  = g_uc [(size_t)base * DI + d];
    float Bv  = g_proj[(size_t)base * PROJW + DTR + n];
    float Cv  = g_proj[(size_t)base * PROJW + DTR + DS + n];
    for (int t = 0; t < Ll; ++t) {
        float dt_c = dtv, u_c = uv, B_c = Bv, C_c = Cv;
        if (t + 1 < Ll) {
            dtv = g_dt [(size_t)(base + t + 1) * DI + d];
            uv  = g_uc [(size_t)(base + t + 1) * DI + d];
            Bv  = g_proj[(size_t)(base + t + 1) * PROJW + DTR + n];
            Cv  = g_proj[(size_t)(base + t + 1) * PROJW + DTR + DS + n];
        }
        float dA = __expf(dt_c * Av);
        h = fmaf(h, dA, dt_c * u_c * B_c);
        float yv = h * C_c;
        yv += __shfl_xor_sync(0xffffffffu, yv, 8, 16);
        yv += __shfl_xor_sync(0xffffffffu, yv, 4, 16);
        yv += __shfl_xor_sync(0xffffffffu, yv, 2, 16);
        yv += __shfl_xor_sync(0xffffffffu, yv, 1, 16);
        if (n == 0) {
            float zv = g_xz[((size_t)(base + t) << 12) + DI + d];
            float sig = 1.f / (1.f + __expf(-zv));
            g_y[(size_t)(base + t) * DI + d] = (yv + u_c * Dv) * (zv * sig);
        }
    }
}

// ---------------- launch ----------------
extern "C" void kernel_launch(void* const* d_in, const int* in_sizes, int n_in,
                              void* d_out, int out_size) {
    const float* x        = (const float*)d_in[0];
    const float* gamma    = (const float*)d_in[1];
    const float* beta     = (const float*)d_in[2];
    const float* in_w     = (const float*)d_in[3];   // [4096,1024]
    const float* conv_w   = (const float*)d_in[4];   // [2048,4]
    const float* conv_b   = (const float*)d_in[5];
    const float* xproj_w  = (const float*)d_in[6];   // [96,2048]
    const float* dtproj_w = (const float*)d_in[7];   // [2048,64]
    const float* dtproj_b = (const float*)d_in[8];
    const float* A_log    = (const float*)d_in[9];   // [2048,16]
    const float* D_param  = (const float*)d_in[10];
    const float* outw     = (const float*)d_in[11];  // [1024,2048]
    float* out = (float*)d_out;

    float *xn, *xz, *uc, *proj, *dt, *y;
    cudaGetSymbolAddress((void**)&xn,   g_xn);
    cudaGetSymbolAddress((void**)&xz,   g_xz);
    cudaGetSymbolAddress((void**)&uc,   g_uc);
    cudaGetSymbolAddress((void**)&proj, g_proj);
    cudaGetSymbolAddress((void**)&dt,   g_dt);
    cudaGetSymbolAddress((void**)&y,    g_y);

    // 1. layernorm
    ln_kernel<<<NROWS, 256>>>(x, gamma, beta, xn);

    // 2. in_proj: [8192,4096] = xn[8192,1024] * in_w[4096,1024]^T
    gemm_kernel<128,128,8,8,0><<<dim3(2*DI/128, NROWS/128), 256>>>(
        xn, in_w, xz, NROWS, 2*DI, DM, DM, DM, 2*DI, nullptr, nullptr);

    // 3. conv + silu
    conv_silu_kernel<<<(NROWS * DI + 255) / 256, 256>>>(conv_w, conv_b, uc);

    // 4. x_proj: [8192,96] = uc[8192,2048] * xproj_w[96,2048]^T  (BM=64 -> 128 CTAs)
    gemm_kernel<64,128,4,8,0><<<dim3(1, NROWS/64), 256>>>(
        uc, xproj_w, proj, NROWS, PROJW, DI, DI, DI, PROJW, nullptr, nullptr);

    // 5. dt_proj + bias + softplus fused: [8192,2048] = proj[:,:64] * dtproj_w^T
    gemm_kernel<128,128,8,8,1><<<dim3(DI/128, NROWS/128), 256>>>(
        proj, dtproj_w, dt, NROWS, DI, DTR, PROJW, DTR, DI, dtproj_b, nullptr);

    // 6. selective scan (+ u*D + silu(z) fused)
    scan_kernel<<<Bb * DI / 16, 256>>>(A_log, D_param);

    // 7. out_proj + GELU + residual fused, writes d_out directly
    gemm_kernel<128,128,8,8,2><<<dim3(DM/128, NROWS/128), 256>>>(
        y, outw, out, NROWS, DM, DI, DI, DI, DM, nullptr, x);
}

// round 5
// speedup vs baseline: 1.9070x; 1.7127x over previous
#include <cuda_runtime.h>
#include <math.h>
#include <stdint.h>

#define Bb 4
#define Ll 2048
#define DM 1024
#define DI 2048
#define DS 16
#define DCONV 4
#define DTR 64
#define NROWS (Bb*Ll)          // 8192
#define PROJW 96

// ---------------- scratch ----------------
__device__ float g_xn [NROWS * DM];
__device__ float g_xz [NROWS * 2 * DI];
__device__ float g_uc [NROWS * DI];
__device__ float g_proj[NROWS * PROJW];
__device__ float g_dt [NROWS * DI];
__device__ float g_y  [NROWS * DI];

// ---------------- cp.async helpers ----------------
__device__ __forceinline__ void cpa16(uint32_t dst, const float* src, uint32_t srcsize) {
    asm volatile("cp.async.cg.shared.global [%0], [%1], 16, %2;"
                 :: "r"(dst), "l"(__cvta_generic_to_global((const void*)src)), "r"(srcsize)
                 : "memory");
}
#define CPA_COMMIT() asm volatile("cp.async.commit_group;" ::: "memory")
#define CPA_WAIT1()  asm volatile("cp.async.wait_group 1;" ::: "memory")
#define CPA_WAIT0()  asm volatile("cp.async.wait_group 0;" ::: "memory")

// ---------------- LayerNorm ----------------
__global__ void ln_kernel(const float* __restrict__ x,
                          const float* __restrict__ gma,
                          const float* __restrict__ bta,
                          float* __restrict__ xn) {
    int row = blockIdx.x;
    const float4* xr = (const float4*)(x + row * DM);
    float4 v = xr[threadIdx.x];
    float s  = v.x + v.y + v.z + v.w;
    float ss = v.x*v.x + v.y*v.y + v.z*v.z + v.w*v.w;
    #pragma unroll
    for (int o = 16; o; o >>= 1) {
        s  += __shfl_xor_sync(0xffffffffu, s,  o);
        ss += __shfl_xor_sync(0xffffffffu, ss, o);
    }
    __shared__ float sh_s[8], sh_ss[8];
    int wid = threadIdx.x >> 5, lane = threadIdx.x & 31;
    if (lane == 0) { sh_s[wid] = s; sh_ss[wid] = ss; }
    __syncthreads();
    if (threadIdx.x == 0) {
        float a = 0.f, b2 = 0.f;
        #pragma unroll
        for (int i = 0; i < 8; ++i) { a += sh_s[i]; b2 += sh_ss[i]; }
        sh_s[0] = a; sh_ss[0] = b2;
    }
    __syncthreads();
    float mu  = sh_s[0]  * (1.f / DM);
    float var = sh_ss[0] * (1.f / DM) - mu * mu;
    float inv = rsqrtf(var + 1e-5f);
    const float4* gv4 = (const float4*)gma;
    const float4* bv4 = (const float4*)bta;
    float4 gv = gv4[threadIdx.x], bv = bv4[threadIdx.x];
    float4 out;
    out.x = (v.x - mu) * inv * gv.x + bv.x;
    out.y = (v.y - mu) * inv * gv.y + bv.y;
    out.z = (v.z - mu) * inv * gv.z + bv.z;
    out.w = (v.w - mu) * inv * gv.w + bv.w;
    ((float4*)(xn + row * DM))[threadIdx.x] = out;
}

// ---------------- tf32 mma.sync GEMM: C[M,N] = A[M,K] * B[N,K]^T ----------------
// 256 threads, 8 warps in 2x4; warp tile (BM/2)x(BN/4); BK=16.
// EPI: 0 plain, 1 bias+softplus, 2 gelu+residual.
template<int BM_, int BN_, int EPI>
__global__ __launch_bounds__(256, 2)
void mma_gemm(const float* __restrict__ A, const float* __restrict__ B,
              float* __restrict__ C, int M, int N, int K,
              int lda, int ldb, int ldc,
              const float* __restrict__ bias, const float* __restrict__ res) {
    constexpr int BK_ = 16, LDS_ = 20;          // stride 20 -> conflict-free frags
    constexpr int WM = 2, WN = 4;
    constexpr int WTM = BM_ / WM, WTN = BN_ / WN;
    constexpr int MT = WTM / 16, NT = WTN / 8;
    constexpr int ACH = BM_ / 64;               // 16B chunks per thread per stage
    constexpr int BCH = BN_ / 64;

    __shared__ alignas(16) float As[2][BM_][LDS_];
    __shared__ alignas(16) float Bs[2][BN_][LDS_];

    int tid = threadIdx.x, wid = tid >> 5, lane = tid & 31;
    int g = lane >> 2, t4 = lane & 3;
    int wm = wid >> 2, wn = wid & 3;
    int bm = blockIdx.y * BM_, bn = blockIdx.x * BN_;

    uint32_t sA = (uint32_t)__cvta_generic_to_shared(&As[0][0][0]);
    uint32_t sB = (uint32_t)__cvta_generic_to_shared(&Bs[0][0][0]);
    constexpr uint32_t STG_A = BM_ * LDS_ * 4;  // bytes per A stage
    constexpr uint32_t STG_B = BN_ * LDS_ * 4;

    float acc[MT][NT][4];
    #pragma unroll
    for (int i = 0; i < MT; ++i)
        #pragma unroll
        for (int j = 0; j < NT; ++j)
            #pragma unroll
            for (int q = 0; q < 4; ++q) acc[i][j][q] = 0.f;

    auto prefetch = [&](int it) {
        int s = it & 1, k0 = it * BK_;
        #pragma unroll
        for (int c = 0; c < ACH; ++c) {
            int cid = tid + 256 * c; int r = cid >> 2; int q = cid & 3;
            cpa16(sA + s * STG_A + (r * LDS_ + q * 4) * 4,
                  A + (size_t)(bm + r) * lda + k0 + q * 4, 16);
        }
        #pragma unroll
        for (int c = 0; c < BCH; ++c) {
            int cid = tid + 256 * c; int r = cid >> 2; int q = cid & 3;
            int rr = bn + r; uint32_t vs = 16;
            if (rr >= N) { rr = N - 1; vs = 0; }
            cpa16(sB + s * STG_B + (r * LDS_ + q * 4) * 4,
                  B + (size_t)rr * ldb + k0 + q * 4, vs);
        }
    };

    prefetch(0); CPA_COMMIT();

    int nIter = K / BK_;
    for (int it = 0; it < nIter; ++it) {
        if (it + 1 < nIter) { prefetch(it + 1); CPA_COMMIT(); CPA_WAIT1(); }
        else                { CPA_WAIT0(); }
        __syncthreads();

        int s = it & 1;
        #pragma unroll
        for (int k8 = 0; k8 < BK_; k8 += 8) {
            uint32_t a[MT][4], b[NT][2];
            #pragma unroll
            for (int mt = 0; mt < MT; ++mt) {
                int rb = wm * WTM + mt * 16;
                a[mt][0] = __float_as_uint(As[s][rb + g     ][k8 + t4    ]);
                a[mt][1] = __float_as_uint(As[s][rb + g + 8 ][k8 + t4    ]);
                a[mt][2] = __float_as_uint(As[s][rb + g     ][k8 + t4 + 4]);
                a[mt][3] = __float_as_uint(As[s][rb + g + 8 ][k8 + t4 + 4]);
            }
            #pragma unroll
            for (int nt = 0; nt < NT; ++nt) {
                int nb = wn * WTN + nt * 8;
                b[nt][0] = __float_as_uint(Bs[s][nb + g][k8 + t4    ]);
                b[nt][1] = __float_as_uint(Bs[s][nb + g][k8 + t4 + 4]);
            }
            #pragma unroll
            for (int mt = 0; mt < MT; ++mt)
                #pragma unroll
                for (int nt = 0; nt < NT; ++nt)
                    asm volatile(
                        "mma.sync.aligned.m16n8k8.row.col.f32.tf32.tf32.f32 "
                        "{%0,%1,%2,%3}, {%4,%5,%6,%7}, {%8,%9}, {%0,%1,%2,%3};"
                        : "+f"(acc[mt][nt][0]), "+f"(acc[mt][nt][1]),
                          "+f"(acc[mt][nt][2]), "+f"(acc[mt][nt][3])
                        : "r"(a[mt][0]), "r"(a[mt][1]), "r"(a[mt][2]), "r"(a[mt][3]),
                          "r"(b[nt][0]), "r"(b[nt][1]));
        }
        __syncthreads();
    }

    // epilogue
    auto ep = [&](float t, int r, int c) -> float {
        if (EPI == 1) {
            t += bias[c];
            return (t > 20.f) ? t : log1pf(expf(t));
        } else if (EPI == 2) {
            float gg = 0.5f * t * (1.f + erff(t * 0.70710678118654752f));
            return gg + res[(size_t)r * ldc + c];
        }
        return t;
    };
    #pragma unroll
    for (int mt = 0; mt < MT; ++mt) {
        int r0 = bm + wm * WTM + mt * 16 + g;
        #pragma unroll
        for (int nt = 0; nt < NT; ++nt) {
            int cb = bn + wn * WTN + nt * 8 + 2 * t4;
            if (cb < N) {
                float2 v0 = make_float2(ep(acc[mt][nt][0], r0, cb),
                                        ep(acc[mt][nt][1], r0, cb + 1));
                float2 v1 = make_float2(ep(acc[mt][nt][2], r0 + 8, cb),
                                        ep(acc[mt][nt][3], r0 + 8, cb + 1));
                *(float2*)(C + (size_t)r0 * ldc + cb)       = v0;
                *(float2*)(C + (size_t)(r0 + 8) * ldc + cb) = v1;
            }
        }
    }
}

// ---------------- depthwise causal conv (K=4) + SiLU ----------------
__global__ void conv_silu_kernel(const float* __restrict__ cw,
                                 const float* __restrict__ cb,
                                 float* __restrict__ uc) {
    int idx = blockIdx.x * blockDim.x + threadIdx.x;
    if (idx >= NROWS * DI) return;
    int d = idx & (DI - 1);
    int l = (idx >> 11) & (Ll - 1);
    int b = idx >> 22;
    float acc = cb[d];
    const float* base = g_xz + ((size_t)(b * Ll) << 12) + d;
    #pragma unroll
    for (int k = 0; k < DCONV; ++k) {
        int ls = l + k - (DCONV - 1);
        if (ls >= 0) acc = fmaf(base[(size_t)ls << 12], cw[d * DCONV + k], acc);
    }
    float sig = 1.f / (1.f + __expf(-acc));
    uc[idx] = acc * sig;
}

// ---------------- selective scan ----------------
__global__ void scan_kernel(const float* __restrict__ A_log,
                            const float* __restrict__ D_param) {
    int warp = threadIdx.x >> 5;
    int lane = threadIdx.x & 31;
    int half = lane >> 4;
    int n    = lane & 15;
    int ch = blockIdx.x * 16 + warp * 2 + half;
    int b = ch >> 11;
    int d = ch & (DI - 1);
    float Av = -__expf(A_log[d * DS + n]);
    float Dv = D_param[d];
    int base = b * Ll;
    float h = 0.f;
    float dtv = g_dt [(size_t)base * DI + d];
    float uv  = g_uc [(size_t)base * DI + d];
    float Bv  = g_proj[(size_t)base * PROJW + DTR + n];
    float Cv  = g_proj[(size_t)base * PROJW + DTR + DS + n];
    for (int t = 0; t < Ll; ++t) {
        float dt_c = dtv, u_c = uv, B_c = Bv, C_c = Cv;
        if (t + 1 < Ll) {
            dtv = g_dt [(size_t)(base + t + 1) * DI + d];
            uv  = g_uc [(size_t)(base + t + 1) * DI + d];
            Bv  = g_proj[(size_t)(base + t + 1) * PROJW + DTR + n];
            Cv  = g_proj[(size_t)(base + t + 1) * PROJW + DTR + DS + n];
        }
        float dA = __expf(dt_c * Av);
        h = fmaf(h, dA, dt_c * u_c * B_c);
        float yv = h * C_c;
        yv += __shfl_xor_sync(0xffffffffu, yv, 8, 16);
        yv += __shfl_xor_sync(0xffffffffu, yv, 4, 16);
        yv += __shfl_xor_sync(0xffffffffu, yv, 2, 16);
        yv += __shfl_xor_sync(0xffffffffu, yv, 1, 16);
        if (n == 0) {
            float zv = g_xz[((size_t)(base + t) << 12) + DI + d];
            float sig = 1.f / (1.f + __expf(-zv));
            g_y[(size_t)(base + t) * DI + d] = (yv + u_c * Dv) * (zv * sig);
        }
    }
}

// ---------------- launch ----------------
extern "C" void kernel_launch(void* const* d_in, const int* in_sizes, int n_in,
                              void* d_out, int out_size) {
    const float* x        = (const float*)d_in[0];
    const float* gamma    = (const float*)d_in[1];
    const float* beta     = (const float*)d_in[2];
    const float* in_w     = (const float*)d_in[3];   // [4096,1024]
    const float* conv_w   = (const float*)d_in[4];   // [2048,4]
    const float* conv_b   = (const float*)d_in[5];
    const float* xproj_w  = (const float*)d_in[6];   // [96,2048]
    const float* dtproj_w = (const float*)d_in[7];   // [2048,64]
    const float* dtproj_b = (const float*)d_in[8];
    const float* A_log    = (const float*)d_in[9];   // [2048,16]
    const float* D_param  = (const float*)d_in[10];
    const float* outw     = (const float*)d_in[11];  // [1024,2048]
    float* out = (float*)d_out;

    float *xn, *xz, *uc, *proj, *dt, *y;
    cudaGetSymbolAddress((void**)&xn,   g_xn);
    cudaGetSymbolAddress((void**)&xz,   g_xz);
    cudaGetSymbolAddress((void**)&uc,   g_uc);
    cudaGetSymbolAddress((void**)&proj, g_proj);
    cudaGetSymbolAddress((void**)&dt,   g_dt);
    cudaGetSymbolAddress((void**)&y,    g_y);

    // 1. layernorm
    ln_kernel<<<NROWS, 256>>>(x, gamma, beta, xn);

    // 2. in_proj: [8192,4096] = xn * in_w^T
    mma_gemm<128,128,0><<<dim3(2*DI/128, NROWS/128), 256>>>(
        xn, in_w, xz, NROWS, 2*DI, DM, DM, DM, 2*DI, nullptr, nullptr);

    // 3. conv + silu
    conv_silu_kernel<<<(NROWS * DI + 255) / 256, 256>>>(conv_w, conv_b, uc);

    // 4. x_proj: [8192,96] = uc * xproj_w^T  (BM=64 -> 128 CTAs)
    mma_gemm<64,128,0><<<dim3(1, NROWS/64), 256>>>(
        uc, xproj_w, proj, NROWS, PROJW, DI, DI, DI, PROJW, nullptr, nullptr);

    // 5. dt_proj + bias + softplus fused: [8192,2048] = proj[:,:64] * dtproj_w^T
    mma_gemm<128,128,1><<<dim3(DI/128, NROWS/128), 256>>>(
        proj, dtproj_w, dt, NROWS, DI, DTR, PROJW, DTR, DI, dtproj_b, nullptr);

    // 6. selective scan (+ u*D + silu(z) fused)
    scan_kernel<<<Bb * DI / 16, 256>>>(A_log, D_param);

    // 7. out_proj + GELU + residual fused, writes d_out
    mma_gemm<128,128,2><<<dim3(DM/128, NROWS/128), 256>>>(
        y, outw, out, NROWS, DM, DI, DI, DI, DM, nullptr, x);
}

// round 7
// speedup vs baseline: 2.3218x; 1.2175x over previous
#include <cuda_runtime.h>
#include <cuda_bf16.h>
#include <math.h>
#include <stdint.h>

#define Bb 4
#define Ll 2048
#define DM 1024
#define DI 2048
#define DS 16
#define DCONV 4
#define DTR 64
#define NROWS (Bb*Ll)          // 8192
#define PROJW 96

// ---------------- scratch ----------------
__device__ float g_xz [NROWS * 2 * DI];    // in_proj out (u | z), f32
__device__ float g_uc [NROWS * DI];        // conv out, f32 (scan)
__device__ float g_proj[NROWS * PROJW];    // x_proj out, f32 (scan B,C)
__device__ float g_dt [NROWS * DI];        // dt after softplus, f32 (scan)
__device__ __nv_bfloat16 g_xn_bf  [NROWS * DM];   // ln out (in_proj A)
__device__ __nv_bfloat16 g_uc_bf  [NROWS * DI];   // conv out (x_proj A)
__device__ __nv_bfloat16 g_dtin_bf[NROWS * DTR];  // dense dt cols (dt_proj A)
__device__ __nv_bfloat16 g_y_bf   [NROWS * DI];   // scan out (out_proj A)
__device__ __nv_bfloat16 g_w_in  [2 * DI * DM];
__device__ __nv_bfloat16 g_w_xp  [PROJW * DI];
__device__ __nv_bfloat16 g_w_dt  [DI * DTR];
__device__ __nv_bfloat16 g_w_out [DM * DI];

// ---------------- cp.async ----------------
__device__ __forceinline__ void cpa16(uint32_t dst, const void* src, uint32_t srcsize) {
    asm volatile("cp.async.cg.shared.global [%0], [%1], 16, %2;"
                 :: "r"(dst), "l"(__cvta_generic_to_global(src)), "r"(srcsize) : "memory");
}
#define CPA_COMMIT() asm volatile("cp.async.commit_group;" ::: "memory")
#define CPA_WAIT1()  asm volatile("cp.async.wait_group 1;" ::: "memory")
#define CPA_WAIT0()  asm volatile("cp.async.wait_group 0;" ::: "memory")

__device__ __forceinline__ void ldm4(uint32_t& r0, uint32_t& r1, uint32_t& r2, uint32_t& r3,
                                     uint32_t addr) {
    asm volatile("ldmatrix.sync.aligned.m8n8.x4.shared.b16 {%0,%1,%2,%3}, [%4];"
                 : "=r"(r0), "=r"(r1), "=r"(r2), "=r"(r3) : "r"(addr));
}

// ---------------- f32 -> bf16 convert ----------------
__global__ void f2b_kernel(const float* __restrict__ in, __nv_bfloat16* __restrict__ out, int n) {
    int i = (blockIdx.x * blockDim.x + threadIdx.x) * 4;
    if (i >= n) return;
    float4 v = *(const float4*)(in + i);
    __nv_bfloat162 lo = __floats2bfloat162_rn(v.x, v.y);
    __nv_bfloat162 hi = __floats2bfloat162_rn(v.z, v.w);
    *(__nv_bfloat162*)(out + i)     = lo;
    *(__nv_bfloat162*)(out + i + 2) = hi;
}

// ---------------- LayerNorm -> bf16 ----------------
__global__ void ln_kernel(const float* __restrict__ x,
                          const float* __restrict__ gma,
                          const float* __restrict__ bta,
                          __nv_bfloat16* __restrict__ xn) {
    int row = blockIdx.x;
    const float4* xr = (const float4*)(x + (size_t)row * DM);
    float4 v = xr[threadIdx.x];
    float s  = v.x + v.y + v.z + v.w;
    float ss = v.x*v.x + v.y*v.y + v.z*v.z + v.w*v.w;
    #pragma unroll
    for (int o = 16; o; o >>= 1) {
        s  += __shfl_xor_sync(0xffffffffu, s,  o);
        ss += __shfl_xor_sync(0xffffffffu, ss, o);
    }
    __shared__ float sh_s[8], sh_ss[8];
    int wid = threadIdx.x >> 5, lane = threadIdx.x & 31;
    if (lane == 0) { sh_s[wid] = s; sh_ss[wid] = ss; }
    __syncthreads();
    if (threadIdx.x == 0) {
        float a = 0.f, b2 = 0.f;
        #pragma unroll
        for (int i = 0; i < 8; ++i) { a += sh_s[i]; b2 += sh_ss[i]; }
        sh_s[0] = a; sh_ss[0] = b2;
    }
    __syncthreads();
    float mu  = sh_s[0]  * (1.f / DM);
    float var = sh_ss[0] * (1.f / DM) - mu * mu;
    float inv = rsqrtf(var + 1e-5f);
    float4 gv = ((const float4*)gma)[threadIdx.x];
    float4 bv = ((const float4*)bta)[threadIdx.x];
    float o0 = (v.x - mu) * inv * gv.x + bv.x;
    float o1 = (v.y - mu) * inv * gv.y + bv.y;
    float o2 = (v.z - mu) * inv * gv.z + bv.z;
    float o3 = (v.w - mu) * inv * gv.w + bv.w;
    __nv_bfloat16* orow = xn + (size_t)row * DM + threadIdx.x * 4;
    *(__nv_bfloat162*)(orow)     = __floats2bfloat162_rn(o0, o1);
    *(__nv_bfloat162*)(orow + 2) = __floats2bfloat162_rn(o2, o3);
}

// ---------------- bf16 mma.sync GEMM: C[M,N] = A[M,K] * B[N,K]^T ----------------
// 256 threads, 8 warps (2 x 4), warp tile (BM/2)x32, BK=32, ldmatrix operands.
// EPI: 0 plain f32, 1 bias+softplus f32, 2 gelu+residual f32, 3 f32 + bf16 dt cols.
template<int BM_, int EPI>
__global__ __launch_bounds__(256, 2)
void mma_gemm(const __nv_bfloat16* __restrict__ A, const __nv_bfloat16* __restrict__ B,
              float* __restrict__ C, int M, int N, int K,
              int lda, int ldb, int ldc,
              const float* __restrict__ bias, const float* __restrict__ res,
              __nv_bfloat16* __restrict__ aux) {
    constexpr int BN_ = 128, BK_ = 32;
    constexpr int STRB = BK_ * 2 + 16;            // 80 B row stride (conflict-free)
    constexpr int WM = 2, WN = 4;
    constexpr int WTM = BM_ / WM;                 // 64 or 32
    constexpr int MT = WTM / 16, NT = 4;          // 32 cols per warp
    constexpr int ACH = BM_ / 64;                 // 16B tasks/thread/stage for A
    constexpr int BCH = BN_ / 64;

    __shared__ alignas(16) char sm[2 * (BM_ + BN_) * STRB];
    uint32_t sA = (uint32_t)__cvta_generic_to_shared(sm);
    uint32_t sB = sA + 2 * BM_ * STRB;
    constexpr uint32_t STG_A = BM_ * STRB, STG_B = BN_ * STRB;

    int tid = threadIdx.x, wid = tid >> 5, lane = tid & 31;
    int g = lane >> 2, t4 = lane & 3;
    int wm = wid >> 2, wn = wid & 3;
    int bm = blockIdx.y * BM_, bn = blockIdx.x * BN_;

    float acc[MT][NT][4];
    #pragma unroll
    for (int i = 0; i < MT; ++i)
        #pragma unroll
        for (int j = 0; j < NT; ++j)
            #pragma unroll
            for (int q = 0; q < 4; ++q) acc[i][j][q] = 0.f;

    auto prefetch = [&](int it) {
        int s = it & 1, k0 = it * BK_;
        #pragma unroll
        for (int c = 0; c < ACH; ++c) {
            int cid = tid + 256 * c; int r = cid >> 2; int q = cid & 3;
            cpa16(sA + s * STG_A + r * STRB + q * 16,
                  A + (size_t)(bm + r) * lda + k0 + q * 8, 16);
        }
        #pragma unroll
        for (int c = 0; c < BCH; ++c) {
            int cid = tid + 256 * c; int r = cid >> 2; int q = cid & 3;
            int rr = bn + r; uint32_t vs = 16;
            if (rr >= N) { rr = N - 1; vs = 0; }
            cpa16(sB + s * STG_B + r * STRB + q * 16,
                  B + (size_t)rr * ldb + k0 + q * 8, vs);
        }
    };

    prefetch(0); CPA_COMMIT();

    // per-lane ldmatrix address offsets (within stage)
    int a_row = wm * WTM + (lane & 15);           // + mt*16
    int a_kb  = (lane >> 4) * 16;                 // bytes: (lane>>4)*8 elems
    int b_row = wn * 32 + ((lane >> 4) << 3) + (lane & 7);  // + nt2*16
    int b_kb  = ((lane >> 3) & 1) * 16;

    int nIter = K / BK_;
    for (int it = 0; it < nIter; ++it) {
        if (it + 1 < nIter) { prefetch(it + 1); CPA_COMMIT(); CPA_WAIT1(); }
        else                { CPA_WAIT0(); }
        __syncthreads();
        int s = it & 1;
        uint32_t baseA = sA + s * STG_A, baseB = sB + s * STG_B;
        #pragma unroll
        for (int k16 = 0; k16 < BK_; k16 += 16) {
            uint32_t a[MT][4], b[NT][2];
            #pragma unroll
            for (int mt = 0; mt < MT; ++mt)
                ldm4(a[mt][0], a[mt][1], a[mt][2], a[mt][3],
                     baseA + (a_row + mt * 16) * STRB + k16 * 2 + a_kb);
            #pragma unroll
            for (int nt2 = 0; nt2 < NT / 2; ++nt2)
                ldm4(b[2*nt2][0], b[2*nt2][1], b[2*nt2+1][0], b[2*nt2+1][1],
                     baseB + (b_row + nt2 * 16) * STRB + k16 * 2 + b_kb);
            #pragma unroll
            for (int mt = 0; mt < MT; ++mt)
                #pragma unroll
                for (int nt = 0; nt < NT; ++nt)
                    asm volatile(
                        "mma.sync.aligned.m16n8k16.row.col.f32.bf16.bf16.f32 "
                        "{%0,%1,%2,%3}, {%4,%5,%6,%7}, {%8,%9}, {%0,%1,%2,%3};"
                        : "+f"(acc[mt][nt][0]), "+f"(acc[mt][nt][1]),
                          "+f"(acc[mt][nt][2]), "+f"(acc[mt][nt][3])
                        : "r"(a[mt][0]), "r"(a[mt][1]), "r"(a[mt][2]), "r"(a[mt][3]),
                          "r"(b[nt][0]), "r"(b[nt][1]));
        }
        __syncthreads();
    }

    auto ep = [&](float t, int r, int c) -> float {
        if (EPI == 1) {
            t += bias[c];
            return (t > 20.f) ? t : log1pf(expf(t));
        } else if (EPI == 2) {
            float gg = 0.5f * t * (1.f + erff(t * 0.70710678118654752f));
            return gg + res[(size_t)r * ldc + c];
        }
        return t;
    };
    #pragma unroll
    for (int mt = 0; mt < MT; ++mt) {
        int r0 = bm + wm * WTM + mt * 16 + g;
        #pragma unroll
        for (int nt = 0; nt < NT; ++nt) {
            int cb = bn + wn * 32 + nt * 8 + 2 * t4;
            if (cb < N) {
                float v00 = ep(acc[mt][nt][0], r0, cb);
                float v01 = ep(acc[mt][nt][1], r0, cb + 1);
                float v10 = ep(acc[mt][nt][2], r0 + 8, cb);
                float v11 = ep(acc[mt][nt][3], r0 + 8, cb + 1);
                *(float2*)(C + (size_t)r0 * ldc + cb)       = make_float2(v00, v01);
                *(float2*)(C + (size_t)(r0 + 8) * ldc + cb) = make_float2(v10, v11);
                if (EPI == 3 && cb < DTR) {
                    *(__nv_bfloat162*)(aux + (size_t)r0 * DTR + cb) =
                        __floats2bfloat162_rn(v00, v01);
                    *(__nv_bfloat162*)(aux + (size_t)(r0 + 8) * DTR + cb) =
                        __floats2bfloat162_rn(v10, v11);
                }
            }
        }
    }
}

// ---------------- depthwise causal conv (K=4) + SiLU -> f32 + bf16 ----------------
__global__ void conv_silu_kernel(const float* __restrict__ cw,
                                 const float* __restrict__ cb) {
    int idx = blockIdx.x * blockDim.x + threadIdx.x;
    if (idx >= NROWS * DI) return;
    int d = idx & (DI - 1);
    int l = (idx >> 11) & (Ll - 1);
    int b = idx >> 22;
    float acc = cb[d];
    const float* base = g_xz + ((size_t)(b * Ll) << 12) + d;
    #pragma unroll
    for (int k = 0; k < DCONV; ++k) {
        int ls = l + k - (DCONV - 1);
        if (ls >= 0) acc = fmaf(base[(size_t)ls << 12], cw[d * DCONV + k], acc);
    }
    float sig = 1.f / (1.f + __expf(-acc));
    float v = acc * sig;
    g_uc[idx] = v;
    g_uc_bf[idx] = __float2bfloat16(v);
}

// ---------------- selective scan -> y bf16 ----------------
__global__ void scan_kernel(const float* __restrict__ A_log,
                            const float* __restrict__ D_param) {
    int warp = threadIdx.x >> 5;
    int lane = threadIdx.x & 31;
    int half = lane >> 4;
    int n    = lane & 15;
    int ch = blockIdx.x * 16 + warp * 2 + half;
    int b = ch >> 11;
    int d = ch & (DI - 1);
    float Av = -__expf(A_log[d * DS + n]);
    float Dv = D_param[d];
    int base = b * Ll;
    float h = 0.f;
    float dtv = g_dt [(size_t)base * DI + d];
    float uv  = g_uc [(size_t)base * DI + d];
    float Bv  = g_proj[(size_t)base * PROJW + DTR + n];
    float Cv  = g_proj[(size_t)base * PROJW + DTR + DS + n];
    for (int t = 0; t < Ll; ++t) {
        float dt_c = dtv, u_c = uv, B_c = Bv, C_c = Cv;
        if (t + 1 < Ll) {
            dtv = g_dt [(size_t)(base + t + 1) * DI + d];
            uv  = g_uc [(size_t)(base + t + 1) * DI + d];
            Bv  = g_proj[(size_t)(base + t + 1) * PROJW + DTR + n];
            Cv  = g_proj[(size_t)(base + t + 1) * PROJW + DTR + DS + n];
        }
        float dA = __expf(dt_c * Av);
        h = fmaf(h, dA, dt_c * u_c * B_c);
        float yv = h * C_c;
        yv += __shfl_xor_sync(0xffffffffu, yv, 8, 16);
        yv += __shfl_xor_sync(0xffffffffu, yv, 4, 16);
        yv += __shfl_xor_sync(0xffffffffu, yv, 2, 16);
        yv += __shfl_xor_sync(0xffffffffu, yv, 1, 16);
        if (n == 0) {
            float zv = g_xz[((size_t)(base + t) << 12) + DI + d];
            float sig = 1.f / (1.f + __expf(-zv));
            g_y_bf[(size_t)(base + t) * DI + d] =
                __float2bfloat16((yv + u_c * Dv) * (zv * sig));
        }
    }
}

// ---------------- launch ----------------
extern "C" void kernel_launch(void* const* d_in, const int* in_sizes, int n_in,
                              void* d_out, int out_size) {
    const float* x        = (const float*)d_in[0];
    const float* gamma    = (const float*)d_in[1];
    const float* beta     = (const float*)d_in[2];
    const float* in_w     = (const float*)d_in[3];   // [4096,1024]
    const float* conv_w   = (const float*)d_in[4];
    const float* conv_b   = (const float*)d_in[5];
    const float* xproj_w  = (const float*)d_in[6];   // [96,2048]
    const float* dtproj_w = (const float*)d_in[7];   // [2048,64]
    const float* dtproj_b = (const float*)d_in[8];
    const float* A_log    = (const float*)d_in[9];
    const float* D_param  = (const float*)d_in[10];
    const float* outw     = (const float*)d_in[11];  // [1024,2048]
    float* out = (float*)d_out;

    float *xz, *uc, *proj, *dt;
    __nv_bfloat16 *xn_bf, *uc_bf, *dtin_bf, *y_bf, *w_in, *w_xp, *w_dt, *w_out;
    cudaGetSymbolAddress((void**)&xz,     g_xz);
    cudaGetSymbolAddress((void**)&uc,     g_uc);
    cudaGetSymbolAddress((void**)&proj,   g_proj);
    cudaGetSymbolAddress((void**)&dt,     g_dt);
    cudaGetSymbolAddress((void**)&xn_bf,  g_xn_bf);
    cudaGetSymbolAddress((void**)&uc_bf,  g_uc_bf);
    cudaGetSymbolAddress((void**)&dtin_bf,g_dtin_bf);
    cudaGetSymbolAddress((void**)&y_bf,   g_y_bf);
    cudaGetSymbolAddress((void**)&w_in,   g_w_in);
    cudaGetSymbolAddress((void**)&w_xp,   g_w_xp);
    cudaGetSymbolAddress((void**)&w_dt,   g_w_dt);
    cudaGetSymbolAddress((void**)&w_out,  g_w_out);

    // 0. weight conversion (f32 -> bf16)
    f2b_kernel<<<(2*DI*DM/4 + 255)/256, 256>>>(in_w,    w_in,  2*DI*DM);
    f2b_kernel<<<(PROJW*DI/4 + 255)/256, 256>>>(xproj_w, w_xp,  PROJW*DI);
    f2b_kernel<<<(DI*DTR/4   + 255)/256, 256>>>(dtproj_w,w_dt,  DI*DTR);
    f2b_kernel<<<(DM*DI/4    + 255)/256, 256>>>(outw,    w_out, DM*DI);

    // 1. layernorm -> bf16
    ln_kernel<<<NROWS, 256>>>(x, gamma, beta, xn_bf);

    // 2. in_proj: [8192,4096] = xn * in_w^T -> f32 xz
    mma_gemm<128,0><<<dim3(2*DI/128, NROWS/128), 256>>>(
        xn_bf, w_in, xz, NROWS, 2*DI, DM, DM, DM, 2*DI, nullptr, nullptr, nullptr);

    // 3. conv + silu -> uc f32 + bf16
    conv_silu_kernel<<<(NROWS * DI + 255) / 256, 256>>>(conv_w, conv_b);

    // 4. x_proj: [8192,96] = uc * xproj_w^T -> f32 proj + dense bf16 dt cols
    mma_gemm<64,3><<<dim3(1, NROWS/64), 256>>>(
        uc_bf, w_xp, proj, NROWS, PROJW, DI, DI, DI, PROJW, nullptr, nullptr, dtin_bf);

    // 5. dt_proj + bias + softplus: [8192,2048] = dtin * dtproj_w^T -> f32 dt
    mma_gemm<128,1><<<dim3(DI/128, NROWS/128), 256>>>(
        dtin_bf, w_dt, dt, NROWS, DI, DTR, DTR, DTR, DI, dtproj_b, nullptr, nullptr);

    // 6. selective scan -> y bf16
    scan_kernel<<<Bb * DI / 16, 256>>>(A_log, D_param);

    // 7. out_proj + GELU + residual -> d_out
    mma_gemm<128,2><<<dim3(DM/128, NROWS/128), 256>>>(
        y_bf, w_out, out, NROWS, DM, DI, DI, DI, DM, nullptr, x, nullptr);
}